// round 12
// baseline (speedup 1.0000x reference)
#include <cuda_runtime.h>

// RandFlow: depthwise 41x41 Gaussian (sigma=5) of flow = 2*noise-1, separable.
// R12 = R11 + taps moved to __constant__ memory (packed float2). Literal-index
// const loads become uniform LDCU -> UR pair, so FFMA2 takes a UR operand:
// only 2 distinct even + 2 distinct odd GPRs -> rt=2 (vs rt=3 bank cap with
// three GPR pairs). Structure otherwise identical to R11 (best: 31.2us).

#define IMG_H 512
#define IMG_W 512
#define IMG_B 16

__device__ unsigned long long g_scratch[IMG_B * IMG_H * IMG_W]; // float2 as u64

#define G0  0.00033546f
#define G1  0.00073182f
#define G2  0.00153381f
#define G3  0.00308872f
#define G4  0.00597603f
#define G5  0.01110900f
#define G6  0.01984110f
#define G7  0.03404746f
#define G8  0.05613476f
#define G9  0.08892166f
#define G10 0.13533528f
#define G11 0.19789871f
#define G12 0.27803730f
#define G13 0.37531110f
#define G14 0.48675226f
#define G15 0.60653066f
#define G16 0.72614904f
#define G17 0.83527021f
#define G18 0.92311635f
#define G19 0.98019867f
#define G20 1.00000000f

// packed (g,g) taps in constant memory -> uniform-path loads at runtime
__constant__ float2 cGK2[41] = {
    {G0,G0},{G1,G1},{G2,G2},{G3,G3},{G4,G4},{G5,G5},{G6,G6},{G7,G7},
    {G8,G8},{G9,G9},{G10,G10},{G11,G11},{G12,G12},{G13,G13},{G14,G14},
    {G15,G15},{G16,G16},{G17,G17},{G18,G18},{G19,G19},{G20,G20},
    {G19,G19},{G18,G18},{G17,G17},{G16,G16},{G15,G15},{G14,G14},{G13,G13},
    {G12,G12},{G11,G11},{G10,G10},{G9,G9},{G8,G8},{G7,G7},{G6,G6},
    {G5,G5},{G4,G4},{G3,G3},{G2,G2},{G1,G1},{G0,G0}
};

// fold 1/S^2 (S = 12.5326388) and (2x-1) into pass-1 load
#define SCALE_A 0.012733434f
#define SCALE_B (-0.006366717f)

__device__ __forceinline__ unsigned long long gk(int k) {
    return reinterpret_cast<const unsigned long long*>(cGK2)[k];
}
__device__ __forceinline__ void ffma2(unsigned long long& d,
                                      unsigned long long a,
                                      unsigned long long b) {
    asm("fma.rn.f32x2 %0, %1, %2, %0;" : "+l"(d) : "l"(a), "l"(b));
}

// pass1 skew: f(x) = x + (x>>4); lane base 16t -> 17t (coprime 32)
#define SK1 600   // f(551) = 585, padded

// ---------------- Pass 1: horizontal, 16 out/thread, 1 warp/row ------------
// 128 threads = 4 warps = 4 rows. Grid = 16*512/4 = 2048. Ring W1=20.
#define W1 20
__global__ void __launch_bounds__(128, 5) rf_pass1(const float2* __restrict__ in) {
    __shared__ unsigned long long s[4][SK1];
    const int warp = threadIdx.x >> 5;
    const int t    = threadIdx.x & 31;
    const int row  = blockIdx.x * 4 + warp;    // b*512 + h
    const float2* src = in + (size_t)row * IMG_W;
    unsigned long long* S = s[warp];

    // interior fill: x = 20 + t + 32j -> w = t + 32j in [0,512); MLP=16
    {
        float2 v[16];
#pragma unroll
        for (int j = 0; j < 16; ++j) v[j] = src[t + 32 * j];
#pragma unroll
        for (int j = 0; j < 16; ++j) {
            const int x = 20 + t + 32 * j;
            float vx = fmaf(v[j].x, SCALE_A, SCALE_B);
            float vy = fmaf(v[j].y, SCALE_A, SCALE_B);
            *reinterpret_cast<float2*>(&S[x + (x >> 4)]) = make_float2(vx, vy);
        }
        if (t < 20) {                          // zero edges (incl. skew holes)
            S[t] = 0ull;
            S[t + (t >> 4)] = 0ull;
            const int x = 532 + t;
            S[x + (x >> 4)] = 0ull;
        }
    }
    __syncwarp();

    const int base = t * 17;                   // skewed base (w0 = 16t)
    unsigned long long win[W1], acc[16];
#pragma unroll
    for (int i = 0; i < W1; ++i) win[i] = S[base + i + (i >> 4)];
#pragma unroll
    for (int r = 0; r < 16; ++r) acc[r] = 0ull;

#pragma unroll
    for (int k = 0; k < 41; ++k) {
        const unsigned long long g = gk(k);    // uniform const load -> UR
#pragma unroll
        for (int r = 0; r < 16; ++r) ffma2(acc[r], win[(k + r) % W1], g);
        if (k < 36) {                          // prefetch i = k + 20 (max 55)
            const int i = k + W1;
            win[k % W1] = S[base + i + (i >> 4)];
        }
    }
    __syncwarp();

    // restage at f(16t+r) = 17t + r, then coalesced stores x = t + 32j
#pragma unroll
    for (int r = 0; r < 16; ++r) S[base + r] = acc[r];
    __syncwarp();

    unsigned long long* dst = g_scratch + (size_t)row * IMG_W;
#pragma unroll
    for (int j = 0; j < 16; ++j) {
        const int x = t + 32 * j;
        dst[x] = S[x + (x >> 4)];
    }
}

// ---------------- Pass 2: vertical, 16 out/thread, ring W2=24 --------------
#define W2 24
__global__ void __launch_bounds__(128, 5) rf_pass2(float2* __restrict__ out) {
    const int w  = (blockIdx.x & 3) * 128 + threadIdx.x;
    const int bh = blockIdx.x >> 2;
    const int b  = bh >> 5;
    const int h0 = (bh & 31) * 16;

    const unsigned long long* src =
        g_scratch + (size_t)b * IMG_H * IMG_W + w;

    unsigned long long win[W2], acc[16];
#pragma unroll
    for (int i = 0; i < W2; ++i) {
        const int h = h0 + i - 20;
        win[i] = ((unsigned)h < (unsigned)IMG_H) ? src[(size_t)h * IMG_W] : 0ull;
    }
#pragma unroll
    for (int r = 0; r < 16; ++r) acc[r] = 0ull;

#pragma unroll
    for (int k = 0; k < 41; ++k) {
        const unsigned long long g = gk(k);    // uniform const load -> UR
#pragma unroll
        for (int r = 0; r < 16; ++r) ffma2(acc[r], win[(k + r) % W2], g);
        if (k < 32) {                          // prefetch i = k + 24
            const int h = h0 + k + 4;
            win[k % W2] = ((unsigned)h < (unsigned)IMG_H) ? src[(size_t)h * IMG_W]
                                                          : 0ull;
        }
    }

    unsigned long long* dst = (unsigned long long*)out
                            + ((size_t)b * IMG_H + h0) * IMG_W + w;
#pragma unroll
    for (int r = 0; r < 16; ++r) dst[(size_t)r * IMG_W] = acc[r];
}

extern "C" void kernel_launch(void* const* d_in, const int* in_sizes, int n_in,
                              void* d_out, int out_size) {
    const float2* noise = nullptr;
    for (int i = 0; i < n_in; ++i) {
        if (in_sizes[i] == IMG_B * IMG_H * IMG_W * 2) {
            noise = (const float2*)d_in[i];
            break;
        }
    }
    if (!noise) noise = (const float2*)d_in[n_in - 1];

    rf_pass1<<<IMG_B * IMG_H / 4, 128>>>(noise);
    rf_pass2<<<IMG_B * (IMG_H / 16) * (IMG_W / 128), 128>>>((float2*)d_out);
}